// round 11
// baseline (speedup 1.0000x reference)
#include <cuda_runtime.h>
#include <cuda_bf16.h>
#include <cstdint>

// GroupLinear: y[b, g*64+o] = sum_i x[b, g*64+i] * W[g*64+o, g*64+i]
// 64 independent [8192x64] x [64x64]^T GEMMs, fp32 in/out.
//
// mma.sync.m16n8k16 bf16 (compute_100-safe) with 2-term bf16 split:
//   x = xh+xl, W = wh+wl;  y ~= xh*wh + xh*wl + xl*wh  (drop lo*lo ~2^-16)
// R11: BLK_TOK=128 (warp owns M=32 -> B ldmatrix + W staging amortized 2x;
// R8 ncu showed L1=77.6% binding) + STS.128 staging (half the STS slots).

#define GROUPS     64
#define GS         64
#define BLK_TOK    128
#define THREADS    128
#define IN_CH      4096
#define N_TOKENS   8192

// SMEM (bytes): bf16 tiles, row stride 72 halves (144 B) -> ldmatrix phases
// hit banks 4r..4r+3 for r=0..7: conflict-free.
#define XSTRIDE_H  72
#define ROWB       (XSTRIDE_H * 2)                       // 144 B per row
#define SM_XH      0
#define SM_XL      (SM_XH + BLK_TOK * ROWB)              // 18432
#define SM_WH      (SM_XL + BLK_TOK * ROWB)              // 36864
#define SM_WL      (SM_WH + GS * ROWB)                   // 46080
#define SM_TOTAL   (SM_WL + GS * ROWB)                   // 55296
// Epilogue staging reuses tile space (after syncthreads):
#define YS_STRIDE  68                                    // floats
#define SM_YS      0                                     // 128*68*4 = 34816 B

__device__ __forceinline__ uint32_t smem_u32(const void* p) {
    uint32_t a;
    asm("{ .reg .u64 t; cvta.to.shared.u64 t, %1; cvt.u32.u64 %0, t; }"
        : "=r"(a) : "l"(p));
    return a;
}

__device__ __forceinline__ uint32_t pack_bf16(float a, float b) {
    __nv_bfloat162 t = __floats2bfloat162_rn(a, b);
    return *reinterpret_cast<uint32_t*>(&t);
}
__device__ __forceinline__ void split_bf16(float v, float& hi, float& lo) {
    hi = __bfloat162float(__float2bfloat16(v));
    lo = v - hi;                    // exact residual
}

// Split 8 consecutive floats (two float4) into one uint4 of hi-bf16 and one of lo.
__device__ __forceinline__ void split8(const float4& v0, const float4& v1,
                                       uint4& hp, uint4& lp) {
    float h0,l0,h1,l1,h2,l2,h3,l3,h4,l4,h5,l5,h6,l6,h7,l7;
    split_bf16(v0.x,h0,l0); split_bf16(v0.y,h1,l1);
    split_bf16(v0.z,h2,l2); split_bf16(v0.w,h3,l3);
    split_bf16(v1.x,h4,l4); split_bf16(v1.y,h5,l5);
    split_bf16(v1.z,h6,l6); split_bf16(v1.w,h7,l7);
    hp = make_uint4(pack_bf16(h0,h1), pack_bf16(h2,h3),
                    pack_bf16(h4,h5), pack_bf16(h6,h7));
    lp = make_uint4(pack_bf16(l0,l1), pack_bf16(l2,l3),
                    pack_bf16(l4,l5), pack_bf16(l6,l7));
}

__device__ __forceinline__ uint4 ldm_x4(uint32_t addr) {
    uint4 r;
    asm volatile("ldmatrix.sync.aligned.m8n8.x4.shared.b16 {%0,%1,%2,%3}, [%4];"
                 : "=r"(r.x), "=r"(r.y), "=r"(r.z), "=r"(r.w) : "r"(addr));
    return r;
}

__device__ __forceinline__ void mma_bf16(float* c, const uint4& a,
                                         uint32_t b0, uint32_t b1) {
    asm volatile(
        "mma.sync.aligned.m16n8k16.row.col.f32.bf16.bf16.f32 "
        "{%0,%1,%2,%3}, {%4,%5,%6,%7}, {%8,%9}, {%0,%1,%2,%3};"
        : "+f"(c[0]), "+f"(c[1]), "+f"(c[2]), "+f"(c[3])
        : "r"(a.x), "r"(a.y), "r"(a.z), "r"(a.w), "r"(b0), "r"(b1));
}

__global__ __launch_bounds__(THREADS, 3)
void group_linear_mma(const float* __restrict__ x,
                      const float* __restrict__ w,
                      float* __restrict__ y) {
    extern __shared__ char smem[];
    const uint32_t sb = smem_u32(smem);
    const int tid  = threadIdx.x;
    const int wid  = tid >> 5;
    const int lane = tid & 31;
    const int g    = blockIdx.y;
    const int tok0 = blockIdx.x * BLK_TOK;

    // ---- Load W diagonal block g -> bf16 hi/lo smem ----
    // 64 rows x 8 chunks of 8 floats = 512 chunks; 4 per thread. STS.128.
    {
        #pragma unroll
        for (int r = 0; r < 4; r++) {
            int idx = tid + r * THREADS;            // 0..511
            int row = idx >> 3;                     // 0..63 (output o)
            int j   = idx & 7;                      // 8-float chunk
            const float4* src = reinterpret_cast<const float4*>(
                w + (size_t)(g * GS + row) * IN_CH + g * GS + j * 8);
            uint4 hp, lp;
            split8(src[0], src[1], hp, lp);
            int off = row * ROWB + j * 16;
            *reinterpret_cast<uint4*>(smem + SM_WH + off) = hp;
            *reinterpret_cast<uint4*>(smem + SM_WL + off) = lp;
        }
    }

    // ---- Load x tile [128 x 64] -> bf16 hi/lo smem ----
    // 128 rows x 8 chunks = 1024; 8 per thread. STS.128.
    {
        #pragma unroll
        for (int r = 0; r < 8; r++) {
            int idx = tid + r * THREADS;            // 0..1023
            int row = idx >> 3;                     // 0..127 (token)
            int j   = idx & 7;
            const float4* src = reinterpret_cast<const float4*>(
                x + (size_t)(tok0 + row) * IN_CH + g * GS + j * 8);
            uint4 hp, lp;
            split8(src[0], src[1], hp, lp);
            int off = row * ROWB + j * 16;
            *reinterpret_cast<uint4*>(smem + SM_XH + off) = hp;
            *reinterpret_cast<uint4*>(smem + SM_XL + off) = lp;
        }
    }
    __syncthreads();

    // ---- Mainloop: warp owns M-rows [wid*32, wid*32+32), all N=64 ----
    const int wrow = wid * 32;

    // ldmatrix lane->address maps (canonical m16n8k16 fragment order):
    // A x4: mats {r0-7/k0-7, r8-15/k0-7, r0-7/k8-15, r8-15/k8-15}
    //   row = base + (lane&15), byte = kk*32 + (lane>>4)*16
    const uint32_t a_addr =
        sb + (uint32_t)((wrow + (lane & 15)) * ROWB + (lane >> 4) * 16);
    // B x4 per nt-pair: mats {n0-7/k0-7, n0-7/k8-15, n8-15/k0-7, n8-15/k8-15}
    //   regs -> {b0(nt0), b1(nt0), b0(nt1), b1(nt1)}
    const int n_local = (lane >> 4) * 8 + (lane & 7);
    const uint32_t b_addr =
        sb + (uint32_t)(n_local * ROWB + ((lane >> 3) & 1) * 16);

    float acc[2][8][4];
    #pragma unroll
    for (int mt = 0; mt < 2; mt++)
        #pragma unroll
        for (int nt = 0; nt < 8; nt++)
            #pragma unroll
            for (int i = 0; i < 4; i++)
                acc[mt][nt][i] = 0.0f;

    #pragma unroll
    for (int kk = 0; kk < 4; kk++) {
        const uint32_t kb = kk * 32;               // 16 bf16 = 32 B
        uint4 ah[2], al[2];
        #pragma unroll
        for (int mt = 0; mt < 2; mt++) {
            ah[mt] = ldm_x4(a_addr + SM_XH + mt * 16 * ROWB + kb);
            al[mt] = ldm_x4(a_addr + SM_XL + mt * 16 * ROWB + kb);
        }

        #pragma unroll
        for (int np = 0; np < 4; np++) {
            uint4 bh = ldm_x4(b_addr + SM_WH + np * 16 * ROWB + kb);
            uint4 bl = ldm_x4(b_addr + SM_WL + np * 16 * ROWB + kb);
            #pragma unroll
            for (int mt = 0; mt < 2; mt++) {
                float* c0 = acc[mt][np * 2];
                float* c1 = acc[mt][np * 2 + 1];
                mma_bf16(c0, ah[mt], bh.x, bh.y);    // hi*hi
                mma_bf16(c1, ah[mt], bh.z, bh.w);
                mma_bf16(c0, ah[mt], bl.x, bl.y);    // hi*lo
                mma_bf16(c1, ah[mt], bl.z, bl.w);
                mma_bf16(c0, al[mt], bh.x, bh.y);    // lo*hi
                mma_bf16(c1, al[mt], bh.z, bh.w);
            }
        }
    }

    // ---- Epilogue: stage C to smem (reuse tiles), coalesced STG ----
    __syncthreads();   // all warps done reading tiles

    {
        float* ys = reinterpret_cast<float*>(smem + SM_YS);
        int r0 = wrow + (lane >> 2);
        int c0 = (lane & 3) * 2;
        #pragma unroll
        for (int mt = 0; mt < 2; mt++) {
            #pragma unroll
            for (int nt = 0; nt < 8; nt++) {
                *reinterpret_cast<float2*>(
                    ys + (r0 + mt * 16) * YS_STRIDE + nt * 8 + c0) =
                    make_float2(acc[mt][nt][0], acc[mt][nt][1]);
                *reinterpret_cast<float2*>(
                    ys + (r0 + mt * 16 + 8) * YS_STRIDE + nt * 8 + c0) =
                    make_float2(acc[mt][nt][2], acc[mt][nt][3]);
            }
        }
    }
    __syncthreads();

    // Coalesced store: 16 lanes cover one row's 64 floats
    {
        const float* ys = reinterpret_cast<const float*>(smem + SM_YS);
        #pragma unroll
        for (int r = 0; r < 16; r++) {
            int idx = tid + r * THREADS;            // 0..2047
            int row = idx >> 4;
            int c4  = idx & 15;
            float4 v = *reinterpret_cast<const float4*>(
                ys + row * YS_STRIDE + c4 * 4);
            *reinterpret_cast<float4*>(
                y + (size_t)(tok0 + row) * IN_CH + g * GS + c4 * 4) = v;
        }
    }
}

extern "C" void kernel_launch(void* const* d_in, const int* in_sizes, int n_in,
                              void* d_out, int out_size) {
    const float* x = (const float*)d_in[0];   // [8192, 4096] fp32
    const float* w = (const float*)d_in[1];   // [4096, 4096] fp32
    float* y = (float*)d_out;                 // [8192, 4096] fp32

    cudaFuncSetAttribute(group_linear_mma,
                         cudaFuncAttributeMaxDynamicSharedMemorySize, SM_TOTAL);
    dim3 grid(N_TOKENS / BLK_TOK, GROUPS);    // (64, 64)
    group_linear_mma<<<grid, THREADS, SM_TOTAL>>>(x, w, y);
}

// round 12
// speedup vs baseline: 1.0286x; 1.0286x over previous
#include <cuda_runtime.h>
#include <cuda_bf16.h>
#include <cstdint>

// GroupLinear: y[b, g*64+o] = sum_i x[b, g*64+i] * W[g*64+o, g*64+i]
// 64 independent [8192x64] x [64x64]^T GEMMs, fp32 in/out.
//
// mma.sync.m16n8k16 bf16 with 2-term bf16 split (3 MMA terms, err ~2^-17).
// R12: persistent CTAs + cp.async pipeline. Each CTA owns one group and ~14
// 64-token tiles; while tile i runs the MMA mainloop, tile i+1's fp32 x is
// cp.async-streamed into smem (R8/R11 ncu: latency-exposed, no pipe >38%).
// W block is loaded/split once per CTA lifetime.

#define GROUPS     64
#define GS         64
#define BLK_TOK    64
#define THREADS    128
#define IN_CH      4096
#define N_TOKENS   8192
#define NTILES     (N_TOKENS / BLK_TOK)      // 128 tiles per group
#define GRID_X     9                          // 576 CTAs = 1 wave @ 4/SM

// SMEM (bytes): bf16 tiles row stride 144 B (72 halves) -> ldmatrix
// conflict-free; fp32 stage row stride 272 B (68 floats).
#define XSTRIDE_H  72
#define ROWB       (XSTRIDE_H * 2)                  // 144
#define SM_WH      0                                 // 64*144 = 9216
#define SM_WL      (SM_WH + GS * ROWB)               // 9216
#define SM_XH      (SM_WL + GS * ROWB)               // 18432
#define SM_XL      (SM_XH + BLK_TOK * ROWB)          // 27648
#define SM_XF      (SM_XL + BLK_TOK * ROWB)          // 36864, fp32 stage
#define XF_STRIDE  68                                // floats (272 B/row)
#define SM_TOTAL   (SM_XF + BLK_TOK * XF_STRIDE * 4) // 54272
// y staging reuses XH+XL (18432 B >= 64*68*4 = 17408)
#define SM_YS      SM_XH
#define YS_STRIDE  68

__device__ __forceinline__ uint32_t smem_u32(const void* p) {
    uint32_t a;
    asm("{ .reg .u64 t; cvta.to.shared.u64 t, %1; cvt.u32.u64 %0, t; }"
        : "=r"(a) : "l"(p));
    return a;
}
__device__ __forceinline__ void cp_async16(uint32_t dst, const void* src) {
    asm volatile("cp.async.cg.shared.global [%0], [%1], 16;"
                 :: "r"(dst), "l"(src) : "memory");
}
__device__ __forceinline__ void cp_commit() {
    asm volatile("cp.async.commit_group;" ::: "memory");
}
__device__ __forceinline__ void cp_wait_all() {
    asm volatile("cp.async.wait_group 0;" ::: "memory");
}

__device__ __forceinline__ uint32_t pack_bf16(float a, float b) {
    __nv_bfloat162 t = __floats2bfloat162_rn(a, b);
    return *reinterpret_cast<uint32_t*>(&t);
}
__device__ __forceinline__ void split_bf16(float v, float& hi, float& lo) {
    hi = __bfloat162float(__float2bfloat16(v));
    lo = v - hi;                    // exact residual
}
__device__ __forceinline__ void split8(const float4& v0, const float4& v1,
                                       uint4& hp, uint4& lp) {
    float h0,l0,h1,l1,h2,l2,h3,l3,h4,l4,h5,l5,h6,l6,h7,l7;
    split_bf16(v0.x,h0,l0); split_bf16(v0.y,h1,l1);
    split_bf16(v0.z,h2,l2); split_bf16(v0.w,h3,l3);
    split_bf16(v1.x,h4,l4); split_bf16(v1.y,h5,l5);
    split_bf16(v1.z,h6,l6); split_bf16(v1.w,h7,l7);
    hp = make_uint4(pack_bf16(h0,h1), pack_bf16(h2,h3),
                    pack_bf16(h4,h5), pack_bf16(h6,h7));
    lp = make_uint4(pack_bf16(l0,l1), pack_bf16(l2,l3),
                    pack_bf16(l4,l5), pack_bf16(l6,l7));
}

__device__ __forceinline__ uint4 ldm_x4(uint32_t addr) {
    uint4 r;
    asm volatile("ldmatrix.sync.aligned.m8n8.x4.shared.b16 {%0,%1,%2,%3}, [%4];"
                 : "=r"(r.x), "=r"(r.y), "=r"(r.z), "=r"(r.w) : "r"(addr));
    return r;
}
__device__ __forceinline__ void mma_bf16(float* c, const uint4& a,
                                         uint32_t b0, uint32_t b1) {
    asm volatile(
        "mma.sync.aligned.m16n8k16.row.col.f32.bf16.bf16.f32 "
        "{%0,%1,%2,%3}, {%4,%5,%6,%7}, {%8,%9}, {%0,%1,%2,%3};"
        : "+f"(c[0]), "+f"(c[1]), "+f"(c[2]), "+f"(c[3])
        : "r"(a.x), "r"(a.y), "r"(a.z), "r"(a.w), "r"(b0), "r"(b1));
}

// Prefetch fp32 x tile (64 rows x 64 floats) into SM_XF via cp.async.
__device__ __forceinline__ void prefetch_tile(uint32_t sb, const float* x,
                                              int g, int tok0, int tid) {
    #pragma unroll
    for (int r = 0; r < 8; r++) {
        int idx = tid + r * THREADS;          // 0..1023
        int row = idx >> 4;                   // 0..63
        int k4  = idx & 15;
        const float* src = x + (size_t)(tok0 + row) * IN_CH + g * GS + k4 * 4;
        cp_async16(sb + SM_XF + row * (XF_STRIDE * 4) + k4 * 16, src);
    }
    cp_commit();
}

__global__ __launch_bounds__(THREADS, 4)
void group_linear_mma(const float* __restrict__ x,
                      const float* __restrict__ w,
                      float* __restrict__ y) {
    extern __shared__ char smem[];
    const uint32_t sb = smem_u32(smem);
    const int tid  = threadIdx.x;
    const int wid  = tid >> 5;
    const int lane = tid & 31;
    const int g    = blockIdx.y;
    const int bx   = blockIdx.x;

    // ---- Prologue: prefetch first tile, then stage W (overlaps async) ----
    prefetch_tile(sb, x, g, bx * BLK_TOK, tid);

    // W diagonal block g -> bf16 hi/lo smem. Once per CTA lifetime.
    {
        #pragma unroll
        for (int r = 0; r < 4; r++) {
            int idx = tid + r * THREADS;            // 0..511
            int row = idx >> 3;                     // 0..63
            int j   = idx & 7;                      // 8-float chunk
            const float4* src = reinterpret_cast<const float4*>(
                w + (size_t)(g * GS + row) * IN_CH + g * GS + j * 8);
            uint4 hp, lp;
            split8(src[0], src[1], hp, lp);
            int off = row * ROWB + j * 16;
            *reinterpret_cast<uint4*>(smem + SM_WH + off) = hp;
            *reinterpret_cast<uint4*>(smem + SM_WL + off) = lp;
        }
    }

    // ldmatrix lane->address maps (canonical m16n8k16 fragment order)
    const int wrow = wid * 16;                      // warp owns 16 M-rows
    const uint32_t a_addr =
        sb + (uint32_t)((wrow + (lane & 15)) * ROWB + (lane >> 4) * 16);
    const int n_local = (lane >> 4) * 8 + (lane & 7);
    const uint32_t b_addr =
        sb + (uint32_t)(n_local * ROWB + ((lane >> 3) & 1) * 16);

    // ---- Persistent tile loop ----
    for (int t = bx; t < NTILES; t += GRID_X) {
        const int tok0 = t * BLK_TOK;

        // Wait for tile t's fp32 data; sync also orders last iter's y STG
        // (reads SM_YS == XH/XL) before this iter's convert overwrites it.
        cp_wait_all();
        __syncthreads();

        // Convert fp32 stage -> bf16 hi/lo tiles (512 chunks, 4/thread)
        {
            const float* xf = reinterpret_cast<const float*>(smem + SM_XF);
            #pragma unroll
            for (int r = 0; r < 4; r++) {
                int idx = tid + r * THREADS;        // 0..511
                int row = idx >> 3;                 // 0..63
                int j   = idx & 7;
                const float4* src = reinterpret_cast<const float4*>(
                    xf + row * XF_STRIDE + j * 8);
                uint4 hp, lp;
                split8(src[0], src[1], hp, lp);
                int off = row * ROWB + j * 16;
                *reinterpret_cast<uint4*>(smem + SM_XH + off) = hp;
                *reinterpret_cast<uint4*>(smem + SM_XL + off) = lp;
            }
        }
        __syncthreads();   // XF fully consumed; bf16 tiles ready

        // Kick prefetch of next tile: overlaps the mainloop + epilogue.
        if (t + GRID_X < NTILES)
            prefetch_tile(sb, x, g, (t + GRID_X) * BLK_TOK, tid);

        // ---- Mainloop: warp = 16 M-rows x all N=64 ----
        float acc[8][4];
        #pragma unroll
        for (int nt = 0; nt < 8; nt++)
            #pragma unroll
            for (int i = 0; i < 4; i++)
                acc[nt][i] = 0.0f;

        #pragma unroll
        for (int kk = 0; kk < 4; kk++) {
            const uint32_t kb = kk * 32;            // 16 bf16 = 32 B
            uint4 ah = ldm_x4(a_addr + SM_XH + kb);
            uint4 al = ldm_x4(a_addr + SM_XL + kb);

            #pragma unroll
            for (int np = 0; np < 4; np++) {
                uint4 bh = ldm_x4(b_addr + SM_WH + np * 16 * ROWB + kb);
                uint4 bl = ldm_x4(b_addr + SM_WL + np * 16 * ROWB + kb);
                float* c0 = acc[np * 2];
                float* c1 = acc[np * 2 + 1];
                mma_bf16(c0, ah, bh.x, bh.y);       // hi*hi
                mma_bf16(c1, ah, bh.z, bh.w);
                mma_bf16(c0, ah, bl.x, bl.y);       // hi*lo
                mma_bf16(c1, ah, bl.z, bl.w);
                mma_bf16(c0, al, bh.x, bh.y);       // lo*hi
                mma_bf16(c1, al, bh.z, bh.w);
            }
        }

        // ---- Epilogue: stage C into XH/XL region, coalesced STG ----
        __syncthreads();   // all warps done reading bf16 x tiles

        {
            float* ys = reinterpret_cast<float*>(smem + SM_YS);
            int r0 = wrow + (lane >> 2);
            int c0 = (lane & 3) * 2;
            #pragma unroll
            for (int nt = 0; nt < 8; nt++) {
                *reinterpret_cast<float2*>(ys + r0 * YS_STRIDE + nt * 8 + c0) =
                    make_float2(acc[nt][0], acc[nt][1]);
                *reinterpret_cast<float2*>(ys + (r0 + 8) * YS_STRIDE + nt * 8 + c0) =
                    make_float2(acc[nt][2], acc[nt][3]);
            }
        }
        __syncthreads();

        {
            const float* ys = reinterpret_cast<const float*>(smem + SM_YS);
            #pragma unroll
            for (int r = 0; r < 8; r++) {
                int idx = tid + r * THREADS;        // 0..1023
                int row = idx >> 4;
                int c4  = idx & 15;
                float4 v = *reinterpret_cast<const float4*>(
                    ys + row * YS_STRIDE + c4 * 4);
                *reinterpret_cast<float4*>(
                    y + (size_t)(tok0 + row) * IN_CH + g * GS + c4 * 4) = v;
            }
        }
        // loop-top cp_wait + __syncthreads orders these STG smem reads
        // against next iteration's convert writes.
    }
}

extern "C" void kernel_launch(void* const* d_in, const int* in_sizes, int n_in,
                              void* d_out, int out_size) {
    const float* x = (const float*)d_in[0];   // [8192, 4096] fp32
    const float* w = (const float*)d_in[1];   // [4096, 4096] fp32
    float* y = (float*)d_out;                 // [8192, 4096] fp32

    cudaFuncSetAttribute(group_linear_mma,
                         cudaFuncAttributeMaxDynamicSharedMemorySize, SM_TOTAL);
    dim3 grid(GRID_X, GROUPS);                // (9, 64) persistent CTAs
    group_linear_mma<<<grid, THREADS, SM_TOTAL>>>(x, w, y);
}

// round 13
// speedup vs baseline: 1.2374x; 1.2030x over previous
#include <cuda_runtime.h>
#include <cuda_bf16.h>
#include <cstdint>

// GroupLinear: y[b, g*64+o] = sum_i x[b, g*64+i] * W[g*64+o, g*64+i]
// 64 independent [8192x64] x [64x64]^T GEMMs, fp32 in/out.
//
// mma.sync.m16n8k16 bf16, 2-term bf16 split (3 MMA products, err ~2^-17).
// R13: (a) A-fragments built in REGISTERS straight from the fp32 cp.async
// stage (convert phase + A-ldmatrix deleted); (b) MMA issue reordered so each
// accumulator's 3 dependent HMMAs are spaced 4 apart across 4 independent
// chains (R8-R12 ncu: dur pinned at ~71us by acc dependency chains,
// tensor 34%, issue 20%). Persistent CTAs + cp.async prefetch retained.

#define GROUPS     64
#define GS         64
#define BLK_TOK    64
#define THREADS    128
#define IN_CH      4096
#define N_TOKENS   8192
#define NTILES     (N_TOKENS / BLK_TOK)      // 128 tiles per group
#define GRID_X     9                          // 576 CTAs = 1 wave @ 4/SM

// SMEM (bytes):
//  W bf16 hi/lo tiles: row stride 144 B -> ldmatrix conflict-free.
//  XF fp32 stage: row stride 72 floats (288 B) -> LDS.64 frag loads
//    conflict-free (word bank = 8*(lane/4) + 2*(lane%4) per half-warp phase).
#define XSTRIDE_H  72
#define ROWB       (XSTRIDE_H * 2)                  // 144
#define SM_WH      0                                 // 9216
#define SM_WL      (SM_WH + GS * ROWB)               // 9216
#define SM_XF      (SM_WL + GS * ROWB)               // 18432
#define XF_STRIDE  72                                // floats
#define SM_YS      (SM_XF + BLK_TOK * XF_STRIDE * 4) // 36864
#define YS_STRIDE  68
#define SM_TOTAL   (SM_YS + BLK_TOK * YS_STRIDE * 4) // 54272

__device__ __forceinline__ uint32_t smem_u32(const void* p) {
    uint32_t a;
    asm("{ .reg .u64 t; cvta.to.shared.u64 t, %1; cvt.u32.u64 %0, t; }"
        : "=r"(a) : "l"(p));
    return a;
}
__device__ __forceinline__ void cp_async16(uint32_t dst, const void* src) {
    asm volatile("cp.async.cg.shared.global [%0], [%1], 16;"
                 :: "r"(dst), "l"(src) : "memory");
}
__device__ __forceinline__ void cp_commit() {
    asm volatile("cp.async.commit_group;" ::: "memory");
}
__device__ __forceinline__ void cp_wait_all() {
    asm volatile("cp.async.wait_group 0;" ::: "memory");
}

__device__ __forceinline__ uint32_t pack_bf16(float a, float b) {
    __nv_bfloat162 t = __floats2bfloat162_rn(a, b);
    return *reinterpret_cast<uint32_t*>(&t);
}
__device__ __forceinline__ void split_bf16(float v, float& hi, float& lo) {
    hi = __bfloat162float(__float2bfloat16(v));
    lo = v - hi;                    // exact residual
}
__device__ __forceinline__ void split8(const float4& v0, const float4& v1,
                                       uint4& hp, uint4& lp) {
    float h0,l0,h1,l1,h2,l2,h3,l3,h4,l4,h5,l5,h6,l6,h7,l7;
    split_bf16(v0.x,h0,l0); split_bf16(v0.y,h1,l1);
    split_bf16(v0.z,h2,l2); split_bf16(v0.w,h3,l3);
    split_bf16(v1.x,h4,l4); split_bf16(v1.y,h5,l5);
    split_bf16(v1.z,h6,l6); split_bf16(v1.w,h7,l7);
    hp = make_uint4(pack_bf16(h0,h1), pack_bf16(h2,h3),
                    pack_bf16(h4,h5), pack_bf16(h6,h7));
    lp = make_uint4(pack_bf16(l0,l1), pack_bf16(l2,l3),
                    pack_bf16(l4,l5), pack_bf16(l6,l7));
}
// Split a float2 into packed bf16 hi and lo words.
__device__ __forceinline__ void split2(const float2 v, uint32_t& hp, uint32_t& lp) {
    float h0,l0,h1,l1;
    split_bf16(v.x,h0,l0); split_bf16(v.y,h1,l1);
    hp = pack_bf16(h0,h1); lp = pack_bf16(l0,l1);
}

__device__ __forceinline__ uint4 ldm_x4(uint32_t addr) {
    uint4 r;
    asm volatile("ldmatrix.sync.aligned.m8n8.x4.shared.b16 {%0,%1,%2,%3}, [%4];"
                 : "=r"(r.x), "=r"(r.y), "=r"(r.z), "=r"(r.w) : "r"(addr));
    return r;
}
__device__ __forceinline__ void mma_bf16(float* c, const uint4& a,
                                         uint32_t b0, uint32_t b1) {
    asm volatile(
        "mma.sync.aligned.m16n8k16.row.col.f32.bf16.bf16.f32 "
        "{%0,%1,%2,%3}, {%4,%5,%6,%7}, {%8,%9}, {%0,%1,%2,%3};"
        : "+f"(c[0]), "+f"(c[1]), "+f"(c[2]), "+f"(c[3])
        : "r"(a.x), "r"(a.y), "r"(a.z), "r"(a.w), "r"(b0), "r"(b1));
}

// Prefetch fp32 x tile (64 rows x 64 floats) into SM_XF via cp.async.
__device__ __forceinline__ void prefetch_tile(uint32_t sb, const float* x,
                                              int g, int tok0, int tid) {
    #pragma unroll
    for (int r = 0; r < 8; r++) {
        int idx = tid + r * THREADS;          // 0..1023
        int row = idx >> 4;                   // 0..63
        int k4  = idx & 15;
        const float* src = x + (size_t)(tok0 + row) * IN_CH + g * GS + k4 * 4;
        cp_async16(sb + SM_XF + row * (XF_STRIDE * 4) + k4 * 16, src);
    }
    cp_commit();
}

__global__ __launch_bounds__(THREADS, 4)
void group_linear_mma(const float* __restrict__ x,
                      const float* __restrict__ w,
                      float* __restrict__ y) {
    extern __shared__ char smem[];
    const uint32_t sb = smem_u32(smem);
    const int tid  = threadIdx.x;
    const int wid  = tid >> 5;
    const int lane = tid & 31;
    const int g    = blockIdx.y;
    const int bx   = blockIdx.x;

    // ---- Prologue: prefetch first tile, stage W once (overlaps async) ----
    prefetch_tile(sb, x, g, bx * BLK_TOK, tid);
    {
        #pragma unroll
        for (int r = 0; r < 4; r++) {
            int idx = tid + r * THREADS;            // 0..511
            int row = idx >> 3;                     // 0..63
            int j   = idx & 7;                      // 8-float chunk
            const float4* src = reinterpret_cast<const float4*>(
                w + (size_t)(g * GS + row) * IN_CH + g * GS + j * 8);
            uint4 hp, lp;
            split8(src[0], src[1], hp, lp);
            int off = row * ROWB + j * 16;
            *reinterpret_cast<uint4*>(smem + SM_WH + off) = hp;
            *reinterpret_cast<uint4*>(smem + SM_WL + off) = lp;
        }
    }

    const int wrow = wid * 16;                      // warp owns 16 M-rows
    // B ldmatrix lane->addr (mats {n0-7/k0-7, n0-7/k8-15, n8-15/k0-7, n8-15/k8-15})
    const int n_local = (lane >> 4) * 8 + (lane & 7);
    const uint32_t b_addr =
        sb + (uint32_t)(n_local * ROWB + ((lane >> 3) & 1) * 16);
    // A fragment source coordinates in XF (canonical m16n8k16 A map)
    const int ar = wrow + (lane >> 2);              // rows ar, ar+8
    const int ac = (lane & 3) * 2;                  // k cols ac, ac+1 (+8)

    // ---- Persistent tile loop ----
    for (int t = bx; t < NTILES; t += GRID_X) {
        const int tok0 = t * BLK_TOK;

        cp_wait_all();          // tile t's fp32 x is in XF
        __syncthreads();        // + orders prior iter's YS reads/XF reads

        // ---- Build A fragments in registers from fp32 XF ----
        uint4 AH[4], AL[4];
        {
            const float* xf = reinterpret_cast<const float*>(smem + SM_XF);
            #pragma unroll
            for (int kk = 0; kk < 4; kk++) {
                const float* p0 = xf + ar * XF_STRIDE + kk * 16 + ac;
                const float* p1 = xf + (ar + 8) * XF_STRIDE + kk * 16 + ac;
                float2 f0 = *reinterpret_cast<const float2*>(p0);
                float2 f1 = *reinterpret_cast<const float2*>(p1);
                float2 f2 = *reinterpret_cast<const float2*>(p0 + 8);
                float2 f3 = *reinterpret_cast<const float2*>(p1 + 8);
                split2(f0, AH[kk].x, AL[kk].x);     // rows ar,   k low
                split2(f1, AH[kk].y, AL[kk].y);     // rows ar+8, k low
                split2(f2, AH[kk].z, AL[kk].z);     // rows ar,   k high
                split2(f3, AH[kk].w, AL[kk].w);     // rows ar+8, k high
            }
        }
        __syncthreads();        // XF fully consumed by all warps

        // Kick prefetch of next tile: overlaps mainloop + epilogue.
        if (t + GRID_X < NTILES)
            prefetch_tile(sb, x, g, (t + GRID_X) * BLK_TOK, tid);

        // ---- Mainloop: 4 independent acc chains per np-pair, term-grouped ----
        float acc[8][4];
        #pragma unroll
        for (int nt = 0; nt < 8; nt++)
            #pragma unroll
            for (int i = 0; i < 4; i++)
                acc[nt][i] = 0.0f;

        #pragma unroll
        for (int kk = 0; kk < 4; kk++) {
            const uint32_t kb = kk * 32;            // 16 bf16 = 32 B
            const uint4 ah = AH[kk];
            const uint4 al = AL[kk];
            #pragma unroll
            for (int npp = 0; npp < 2; npp++) {     // np pair {2npp, 2npp+1}
                const uint32_t o0 = (npp * 2) * 16 * ROWB + kb;
                const uint32_t o1 = (npp * 2 + 1) * 16 * ROWB + kb;
                uint4 bh0 = ldm_x4(b_addr + SM_WH + o0);
                uint4 bh1 = ldm_x4(b_addr + SM_WH + o1);
                uint4 bl0 = ldm_x4(b_addr + SM_WL + o0);
                uint4 bl1 = ldm_x4(b_addr + SM_WL + o1);
                float* c0 = acc[npp * 4 + 0];
                float* c1 = acc[npp * 4 + 1];
                float* c2 = acc[npp * 4 + 2];
                float* c3 = acc[npp * 4 + 3];
                // term hi*hi across 4 chains
                mma_bf16(c0, ah, bh0.x, bh0.y);
                mma_bf16(c1, ah, bh0.z, bh0.w);
                mma_bf16(c2, ah, bh1.x, bh1.y);
                mma_bf16(c3, ah, bh1.z, bh1.w);
                // term hi*lo
                mma_bf16(c0, ah, bl0.x, bl0.y);
                mma_bf16(c1, ah, bl0.z, bl0.w);
                mma_bf16(c2, ah, bl1.x, bl1.y);
                mma_bf16(c3, ah, bl1.z, bl1.w);
                // term lo*hi
                mma_bf16(c0, al, bh0.x, bh0.y);
                mma_bf16(c1, al, bh0.z, bh0.w);
                mma_bf16(c2, al, bh1.x, bh1.y);
                mma_bf16(c3, al, bh1.z, bh1.w);
            }
        }

        // ---- Epilogue: stage C to YS, coalesced STG ----
        // acc[npp*4 + j] covers N-cols (npp*2 + j/2)*8 .. +7, j%2 selects
        // the n8-15 half: columns = (npp*16) + (j>>1)*... mapping:
        // chain index c = npp*4 + j -> np = npp*2 + (j>>1), half = j&1 is
        // folded as: c0/c1 from bh0 (np=2npp, n-halves 0/1), c2/c3 from bh1.
        {
            float* ys = reinterpret_cast<float*>(smem + SM_YS);
            int r0 = wrow + (lane >> 2);
            int c0col = (lane & 3) * 2;
            #pragma unroll
            for (int cix = 0; cix < 8; cix++) {
                // n block: npp = cix/4, reg-half = cix%4 -> n0 = npp*32 + (cix%4)*8
                int n0 = (cix >> 2) * 32 + (cix & 3) * 8;
                *reinterpret_cast<float2*>(
                    ys + r0 * YS_STRIDE + n0 + c0col) =
                    make_float2(acc[cix][0], acc[cix][1]);
                *reinterpret_cast<float2*>(
                    ys + (r0 + 8) * YS_STRIDE + n0 + c0col) =
                    make_float2(acc[cix][2], acc[cix][3]);
            }
        }
        __syncthreads();

        {
            const float* ys = reinterpret_cast<const float*>(smem + SM_YS);
            #pragma unroll
            for (int r = 0; r < 8; r++) {
                int idx = tid + r * THREADS;        // 0..1023
                int row = idx >> 4;
                int c4  = idx & 15;
                float4 v = *reinterpret_cast<const float4*>(
                    ys + row * YS_STRIDE + c4 * 4);
                *reinterpret_cast<float4*>(
                    y + (size_t)(tok0 + row) * IN_CH + g * GS + c4 * 4) = v;
            }
        }
        // loop-top syncthreads orders these YS reads vs next iter's writes.
    }
}

extern "C" void kernel_launch(void* const* d_in, const int* in_sizes, int n_in,
                              void* d_out, int out_size) {
    const float* x = (const float*)d_in[0];   // [8192, 4096] fp32
    const float* w = (const float*)d_in[1];   // [4096, 4096] fp32
    float* y = (float*)d_out;                 // [8192, 4096] fp32

    cudaFuncSetAttribute(group_linear_mma,
                         cudaFuncAttributeMaxDynamicSharedMemorySize, SM_TOTAL);
    dim3 grid(GRID_X, GROUPS);                // (9, 64) persistent CTAs
    group_linear_mma<<<grid, THREADS, SM_TOTAL>>>(x, w, y);
}

// round 14
// speedup vs baseline: 1.3295x; 1.0744x over previous
#include <cuda_runtime.h>
#include <cuda_bf16.h>
#include <cstdint>

// GroupLinear: y[b, g*64+o] = sum_i x[b, g*64+i] * W[g*64+o, g*64+i]
// 64 independent [8192x64] x [64x64]^T GEMMs, fp32 in/out.
//
// mma.sync.m16n8k16 bf16, 2-term split: x = xh+xl (TRUNC split, cheap),
// W = wh+wl (rn split, once per CTA); y ~= xh*wh + xh*wl + xl*wh.
// R14 on R13 (59.6us): (a) PRMT/LOP3 truncation split halves A-build instr;
// (b) double-buffered fp32 stage -> cp.async wait is a full iteration deep
// (non-blocking); (c) YS staging reuses the dead current XF buffer.

#define GROUPS     64
#define GS         64
#define BLK_TOK    64
#define THREADS    128
#define IN_CH      4096
#define N_TOKENS   8192
#define NTILES     (N_TOKENS / BLK_TOK)      // 128 tiles per group
#define GRID_X     9                          // 576 CTAs = 1 wave @ 4/SM

// SMEM (bytes):
//  W bf16 hi/lo tiles: row stride 144 B -> ldmatrix conflict-free.
//  XF fp32 stages (x2): row stride 72 floats -> LDS.64 frag loads and
//    epilogue LDS.128/STS.64 all conflict-free (8q+2b / 8r+4c bank maps).
#define XSTRIDE_H  72
#define ROWB       (XSTRIDE_H * 2)                  // 144
#define SM_WH      0                                 // 9216
#define SM_WL      (SM_WH + GS * ROWB)               // 9216
#define XF_STRIDE  72                                // floats
#define XF_BYTES   (BLK_TOK * XF_STRIDE * 4)         // 18432
#define SM_XF0     (SM_WL + GS * ROWB)               // 18432
#define SM_XF1     (SM_XF0 + XF_BYTES)               // 36864
#define SM_TOTAL   (SM_XF1 + XF_BYTES)               // 55296

__device__ __forceinline__ uint32_t smem_u32(const void* p) {
    uint32_t a;
    asm("{ .reg .u64 t; cvta.to.shared.u64 t, %1; cvt.u32.u64 %0, t; }"
        : "=r"(a) : "l"(p));
    return a;
}
__device__ __forceinline__ void cp_async16(uint32_t dst, const void* src) {
    asm volatile("cp.async.cg.shared.global [%0], [%1], 16;"
                 :: "r"(dst), "l"(src) : "memory");
}
__device__ __forceinline__ void cp_commit() {
    asm volatile("cp.async.commit_group;" ::: "memory");
}
__device__ __forceinline__ void cp_wait_all() {
    asm volatile("cp.async.wait_group 0;" ::: "memory");
}

__device__ __forceinline__ uint32_t pack_bf16(float a, float b) {
    __nv_bfloat162 t = __floats2bfloat162_rn(a, b);
    return *reinterpret_cast<uint32_t*>(&t);
}
// rn split (used for W only)
__device__ __forceinline__ void split_bf16(float v, float& hi, float& lo) {
    hi = __bfloat162float(__float2bfloat16(v));
    lo = v - hi;
}
__device__ __forceinline__ void split8(const float4& v0, const float4& v1,
                                       uint4& hp, uint4& lp) {
    float h0,l0,h1,l1,h2,l2,h3,l3,h4,l4,h5,l5,h6,l6,h7,l7;
    split_bf16(v0.x,h0,l0); split_bf16(v0.y,h1,l1);
    split_bf16(v0.z,h2,l2); split_bf16(v0.w,h3,l3);
    split_bf16(v1.x,h4,l4); split_bf16(v1.y,h5,l5);
    split_bf16(v1.z,h6,l6); split_bf16(v1.w,h7,l7);
    hp = make_uint4(pack_bf16(h0,h1), pack_bf16(h2,h3),
                    pack_bf16(h4,h5), pack_bf16(h6,h7));
    lp = make_uint4(pack_bf16(l0,l1), pack_bf16(l2,l3),
                    pack_bf16(l4,l5), pack_bf16(l6,l7));
}
// Truncation split for a float2 (A path): hi = top-16-bits bf16 (exact trunc),
// lo = exact residual rounded to bf16. 6 instr: PRMT + 2 AND + 2 SUB + CVT.
__device__ __forceinline__ void split2t(const float2 v, uint32_t& hp, uint32_t& lp) {
    uint32_t u0 = __float_as_uint(v.x);
    uint32_t u1 = __float_as_uint(v.y);
    hp = __byte_perm(u0, u1, 0x7632);               // {u1.hi16, u0.hi16}
    float h0 = __uint_as_float(u0 & 0xFFFF0000u);
    float h1 = __uint_as_float(u1 & 0xFFFF0000u);
    lp = pack_bf16(v.x - h0, v.y - h1);
}

__device__ __forceinline__ uint4 ldm_x4(uint32_t addr) {
    uint4 r;
    asm volatile("ldmatrix.sync.aligned.m8n8.x4.shared.b16 {%0,%1,%2,%3}, [%4];"
                 : "=r"(r.x), "=r"(r.y), "=r"(r.z), "=r"(r.w) : "r"(addr));
    return r;
}
__device__ __forceinline__ void mma_bf16(float* c, const uint4& a,
                                         uint32_t b0, uint32_t b1) {
    asm volatile(
        "mma.sync.aligned.m16n8k16.row.col.f32.bf16.bf16.f32 "
        "{%0,%1,%2,%3}, {%4,%5,%6,%7}, {%8,%9}, {%0,%1,%2,%3};"
        : "+f"(c[0]), "+f"(c[1]), "+f"(c[2]), "+f"(c[3])
        : "r"(a.x), "r"(a.y), "r"(a.z), "r"(a.w), "r"(b0), "r"(b1));
}

// Prefetch fp32 x tile (64 rows x 64 floats) into an XF buffer via cp.async.
__device__ __forceinline__ void prefetch_tile(uint32_t dst_base, const float* x,
                                              int g, int tok0, int tid) {
    #pragma unroll
    for (int r = 0; r < 8; r++) {
        int idx = tid + r * THREADS;          // 0..1023
        int row = idx >> 4;                   // 0..63
        int k4  = idx & 15;
        const float* src = x + (size_t)(tok0 + row) * IN_CH + g * GS + k4 * 4;
        cp_async16(dst_base + row * (XF_STRIDE * 4) + k4 * 16, src);
    }
    cp_commit();
}

__global__ __launch_bounds__(THREADS, 4)
void group_linear_mma(const float* __restrict__ x,
                      const float* __restrict__ w,
                      float* __restrict__ y) {
    extern __shared__ char smem[];
    const uint32_t sb = smem_u32(smem);
    const int tid  = threadIdx.x;
    const int wid  = tid >> 5;
    const int lane = tid & 31;
    const int g    = blockIdx.y;
    const int bx   = blockIdx.x;

    // ---- Prologue: prefetch first tile into XF0, stage W once ----
    prefetch_tile(sb + SM_XF0, x, g, bx * BLK_TOK, tid);
    {
        #pragma unroll
        for (int r = 0; r < 4; r++) {
            int idx = tid + r * THREADS;            // 0..511
            int row = idx >> 3;                     // 0..63
            int j   = idx & 7;                      // 8-float chunk
            const float4* src = reinterpret_cast<const float4*>(
                w + (size_t)(g * GS + row) * IN_CH + g * GS + j * 8);
            uint4 hp, lp;
            split8(src[0], src[1], hp, lp);
            int off = row * ROWB + j * 16;
            *reinterpret_cast<uint4*>(smem + SM_WH + off) = hp;
            *reinterpret_cast<uint4*>(smem + SM_WL + off) = lp;
        }
    }

    const int wrow = wid * 16;                      // warp owns 16 M-rows
    // B ldmatrix lane->addr (mats {n0-7/k0-7, n0-7/k8-15, n8-15/k0-7, n8-15/k8-15})
    const int n_local = (lane >> 4) * 8 + (lane & 7);
    const uint32_t b_addr =
        sb + (uint32_t)(n_local * ROWB + ((lane >> 3) & 1) * 16);
    // A fragment source coordinates in XF (canonical m16n8k16 A map)
    const int ar = wrow + (lane >> 2);              // rows ar, ar+8
    const int ac = (lane & 3) * 2;                  // k cols ac, ac+1 (+8)

    uint32_t xf_cur  = sb + SM_XF0;
    uint32_t xf_next = sb + SM_XF1;

    // ---- Persistent tile loop ----
    for (int t = bx; t < NTILES; t += GRID_X) {
        const int tok0 = t * BLK_TOK;

        cp_wait_all();          // tile t in xf_cur (in flight a full iter)
        __syncthreads();        // sync #1: also fences prior iter's YS reads
                                // of xf_next (= last iter's xf_cur)

        // Kick next prefetch immediately: full-iteration-deep pipeline.
        if (t + GRID_X < NTILES)
            prefetch_tile(xf_next, x, g, (t + GRID_X) * BLK_TOK, tid);

        // ---- Build A fragments in registers (trunc split) ----
        uint4 AH[4], AL[4];
        {
            const float* xf = reinterpret_cast<const float*>(
                smem + (xf_cur - sb));
            #pragma unroll
            for (int kk = 0; kk < 4; kk++) {
                const float* p0 = xf + ar * XF_STRIDE + kk * 16 + ac;
                const float* p1 = xf + (ar + 8) * XF_STRIDE + kk * 16 + ac;
                float2 f0 = *reinterpret_cast<const float2*>(p0);
                float2 f1 = *reinterpret_cast<const float2*>(p1);
                float2 f2 = *reinterpret_cast<const float2*>(p0 + 8);
                float2 f3 = *reinterpret_cast<const float2*>(p1 + 8);
                split2t(f0, AH[kk].x, AL[kk].x);    // rows ar,   k low
                split2t(f1, AH[kk].y, AL[kk].y);    // rows ar+8, k low
                split2t(f2, AH[kk].z, AL[kk].z);    // rows ar,   k high
                split2t(f3, AH[kk].w, AL[kk].w);    // rows ar+8, k high
            }
        }

        // ---- Mainloop: 4 independent acc chains per np-pair ----
        float acc[8][4];
        #pragma unroll
        for (int nt = 0; nt < 8; nt++)
            #pragma unroll
            for (int i = 0; i < 4; i++)
                acc[nt][i] = 0.0f;

        #pragma unroll
        for (int kk = 0; kk < 4; kk++) {
            const uint32_t kb = kk * 32;            // 16 bf16 = 32 B
            const uint4 ah = AH[kk];
            const uint4 al = AL[kk];
            #pragma unroll
            for (int npp = 0; npp < 2; npp++) {
                const uint32_t o0 = (npp * 2) * 16 * ROWB + kb;
                const uint32_t o1 = (npp * 2 + 1) * 16 * ROWB + kb;
                uint4 bh0 = ldm_x4(b_addr + SM_WH + o0);
                uint4 bh1 = ldm_x4(b_addr + SM_WH + o1);
                uint4 bl0 = ldm_x4(b_addr + SM_WL + o0);
                uint4 bl1 = ldm_x4(b_addr + SM_WL + o1);
                float* c0 = acc[npp * 4 + 0];
                float* c1 = acc[npp * 4 + 1];
                float* c2 = acc[npp * 4 + 2];
                float* c3 = acc[npp * 4 + 3];
                mma_bf16(c0, ah, bh0.x, bh0.y);     // hi*hi
                mma_bf16(c1, ah, bh0.z, bh0.w);
                mma_bf16(c2, ah, bh1.x, bh1.y);
                mma_bf16(c3, ah, bh1.z, bh1.w);
                mma_bf16(c0, ah, bl0.x, bl0.y);     // hi*lo
                mma_bf16(c1, ah, bl0.z, bl0.w);
                mma_bf16(c2, ah, bl1.x, bl1.y);
                mma_bf16(c3, ah, bl1.z, bl1.w);
                mma_bf16(c0, al, bh0.x, bh0.y);     // lo*hi
                mma_bf16(c1, al, bh0.z, bh0.w);
                mma_bf16(c2, al, bh1.x, bh1.y);
                mma_bf16(c3, al, bh1.z, bh1.w);
            }
        }

        // ---- Epilogue: stage C into the (now dead) xf_cur, coalesced STG ----
        __syncthreads();        // sync #2: all warps done reading xf_cur
        {
            float* ys = reinterpret_cast<float*>(smem + (xf_cur - sb));
            int r0 = wrow + (lane >> 2);
            int c0col = (lane & 3) * 2;
            #pragma unroll
            for (int cix = 0; cix < 8; cix++) {
                int n0 = (cix >> 2) * 32 + (cix & 3) * 8;
                *reinterpret_cast<float2*>(
                    ys + r0 * XF_STRIDE + n0 + c0col) =
                    make_float2(acc[cix][0], acc[cix][1]);
                *reinterpret_cast<float2*>(
                    ys + (r0 + 8) * XF_STRIDE + n0 + c0col) =
                    make_float2(acc[cix][2], acc[cix][3]);
            }
        }
        __syncthreads();        // sync #3: YS fully staged
        {
            const float* ys = reinterpret_cast<const float*>(
                smem + (xf_cur - sb));
            #pragma unroll
            for (int r = 0; r < 8; r++) {
                int idx = tid + r * THREADS;        // 0..1023
                int row = idx >> 4;
                int c4  = idx & 15;
                float4 v = *reinterpret_cast<const float4*>(
                    ys + row * XF_STRIDE + c4 * 4);
                *reinterpret_cast<float4*>(
                    y + (size_t)(tok0 + row) * IN_CH + g * GS + c4 * 4) = v;
            }
        }

        // swap buffers; next iter's top sync fences these YS reads before
        // the following prefetch overwrites this buffer.
        uint32_t tmp = xf_cur; xf_cur = xf_next; xf_next = tmp;
    }
}

extern "C" void kernel_launch(void* const* d_in, const int* in_sizes, int n_in,
                              void* d_out, int out_size) {
    const float* x = (const float*)d_in[0];   // [8192, 4096] fp32
    const float* w = (const float*)d_in[1];   // [4096, 4096] fp32
    float* y = (float*)d_out;                 // [8192, 4096] fp32

    cudaFuncSetAttribute(group_linear_mma,
                         cudaFuncAttributeMaxDynamicSharedMemorySize, SM_TOTAL);
    dim3 grid(GRID_X, GROUPS);                // (9, 64) persistent CTAs
    group_linear_mma<<<grid, THREADS, SM_TOTAL>>>(x, w, y);
}

// round 15
// speedup vs baseline: 1.3450x; 1.0117x over previous
#include <cuda_runtime.h>
#include <cuda_bf16.h>
#include <cstdint>

// GroupLinear: y[b, g*64+o] = sum_i x[b, g*64+i] * W[g*64+o, g*64+i]
// 64 independent [8192x64] x [64x64]^T GEMMs, fp32 in/out.
//
// mma.sync.m16n8k16 bf16, 2-term split: x = xh+xl (trunc split),
// W = wh+wl (rn split, once per CTA); y ~= xh*wh + xh*wl + xl*wh.
// R15 on R14 (55.5us): direct register->global epilogue. Stores are
// sector-perfect without staging (8 rows x 32B full sectors per warp
// instruction), so the smem round-trip + 2 of 3 per-tile barriers go away.

#define GROUPS     64
#define GS         64
#define BLK_TOK    64
#define THREADS    128
#define IN_CH      4096
#define N_TOKENS   8192
#define NTILES     (N_TOKENS / BLK_TOK)      // 128 tiles per group
#define GRID_X     9                          // 576 CTAs = 1 wave @ 4/SM

// SMEM (bytes):
//  W bf16 hi/lo tiles: row stride 144 B -> ldmatrix conflict-free.
//  XF fp32 stages (x2): row stride 72 floats -> LDS.64 frag loads
//    conflict-free.
#define XSTRIDE_H  72
#define ROWB       (XSTRIDE_H * 2)                  // 144
#define SM_WH      0                                 // 9216
#define SM_WL      (SM_WH + GS * ROWB)               // 9216
#define XF_STRIDE  72                                // floats
#define XF_BYTES   (BLK_TOK * XF_STRIDE * 4)         // 18432
#define SM_XF0     (SM_WL + GS * ROWB)               // 18432
#define SM_XF1     (SM_XF0 + XF_BYTES)               // 36864
#define SM_TOTAL   (SM_XF1 + XF_BYTES)               // 55296

__device__ __forceinline__ uint32_t smem_u32(const void* p) {
    uint32_t a;
    asm("{ .reg .u64 t; cvta.to.shared.u64 t, %1; cvt.u32.u64 %0, t; }"
        : "=r"(a) : "l"(p));
    return a;
}
__device__ __forceinline__ void cp_async16(uint32_t dst, const void* src) {
    asm volatile("cp.async.cg.shared.global [%0], [%1], 16;"
                 :: "r"(dst), "l"(src) : "memory");
}
__device__ __forceinline__ void cp_commit() {
    asm volatile("cp.async.commit_group;" ::: "memory");
}
__device__ __forceinline__ void cp_wait_all() {
    asm volatile("cp.async.wait_group 0;" ::: "memory");
}

__device__ __forceinline__ uint32_t pack_bf16(float a, float b) {
    __nv_bfloat162 t = __floats2bfloat162_rn(a, b);
    return *reinterpret_cast<uint32_t*>(&t);
}
// rn split (W only, once per CTA)
__device__ __forceinline__ void split_bf16(float v, float& hi, float& lo) {
    hi = __bfloat162float(__float2bfloat16(v));
    lo = v - hi;
}
__device__ __forceinline__ void split8(const float4& v0, const float4& v1,
                                       uint4& hp, uint4& lp) {
    float h0,l0,h1,l1,h2,l2,h3,l3,h4,l4,h5,l5,h6,l6,h7,l7;
    split_bf16(v0.x,h0,l0); split_bf16(v0.y,h1,l1);
    split_bf16(v0.z,h2,l2); split_bf16(v0.w,h3,l3);
    split_bf16(v1.x,h4,l4); split_bf16(v1.y,h5,l5);
    split_bf16(v1.z,h6,l6); split_bf16(v1.w,h7,l7);
    hp = make_uint4(pack_bf16(h0,h1), pack_bf16(h2,h3),
                    pack_bf16(h4,h5), pack_bf16(h6,h7));
    lp = make_uint4(pack_bf16(l0,l1), pack_bf16(l2,l3),
                    pack_bf16(l4,l5), pack_bf16(l6,l7));
}
// Truncation split for a float2 (A path): hi = top 16 bits (exact trunc),
// lo = exact residual rounded to bf16.
__device__ __forceinline__ void split2t(const float2 v, uint32_t& hp, uint32_t& lp) {
    uint32_t u0 = __float_as_uint(v.x);
    uint32_t u1 = __float_as_uint(v.y);
    hp = __byte_perm(u0, u1, 0x7632);               // {u1.hi16, u0.hi16}
    float h0 = __uint_as_float(u0 & 0xFFFF0000u);
    float h1 = __uint_as_float(u1 & 0xFFFF0000u);
    lp = pack_bf16(v.x - h0, v.y - h1);
}

__device__ __forceinline__ uint4 ldm_x4(uint32_t addr) {
    uint4 r;
    asm volatile("ldmatrix.sync.aligned.m8n8.x4.shared.b16 {%0,%1,%2,%3}, [%4];"
                 : "=r"(r.x), "=r"(r.y), "=r"(r.z), "=r"(r.w) : "r"(addr));
    return r;
}
__device__ __forceinline__ void mma_bf16(float* c, const uint4& a,
                                         uint32_t b0, uint32_t b1) {
    asm volatile(
        "mma.sync.aligned.m16n8k16.row.col.f32.bf16.bf16.f32 "
        "{%0,%1,%2,%3}, {%4,%5,%6,%7}, {%8,%9}, {%0,%1,%2,%3};"
        : "+f"(c[0]), "+f"(c[1]), "+f"(c[2]), "+f"(c[3])
        : "r"(a.x), "r"(a.y), "r"(a.z), "r"(a.w), "r"(b0), "r"(b1));
}

// Prefetch fp32 x tile (64 rows x 64 floats) into an XF buffer via cp.async.
__device__ __forceinline__ void prefetch_tile(uint32_t dst_base, const float* x,
                                              int g, int tok0, int tid) {
    #pragma unroll
    for (int r = 0; r < 8; r++) {
        int idx = tid + r * THREADS;          // 0..1023
        int row = idx >> 4;                   // 0..63
        int k4  = idx & 15;
        const float* src = x + (size_t)(tok0 + row) * IN_CH + g * GS + k4 * 4;
        cp_async16(dst_base + row * (XF_STRIDE * 4) + k4 * 16, src);
    }
    cp_commit();
}

__global__ __launch_bounds__(THREADS, 4)
void group_linear_mma(const float* __restrict__ x,
                      const float* __restrict__ w,
                      float* __restrict__ y) {
    extern __shared__ char smem[];
    const uint32_t sb = smem_u32(smem);
    const int tid  = threadIdx.x;
    const int wid  = tid >> 5;
    const int lane = tid & 31;
    const int g    = blockIdx.y;
    const int bx   = blockIdx.x;

    // ---- Prologue: prefetch first tile into XF0, stage W once ----
    prefetch_tile(sb + SM_XF0, x, g, bx * BLK_TOK, tid);
    {
        #pragma unroll
        for (int r = 0; r < 4; r++) {
            int idx = tid + r * THREADS;            // 0..511
            int row = idx >> 3;                     // 0..63
            int j   = idx & 7;                      // 8-float chunk
            const float4* src = reinterpret_cast<const float4*>(
                w + (size_t)(g * GS + row) * IN_CH + g * GS + j * 8);
            uint4 hp, lp;
            split8(src[0], src[1], hp, lp);
            int off = row * ROWB + j * 16;
            *reinterpret_cast<uint4*>(smem + SM_WH + off) = hp;
            *reinterpret_cast<uint4*>(smem + SM_WL + off) = lp;
        }
    }

    const int wrow = wid * 16;                      // warp owns 16 M-rows
    // B ldmatrix lane->addr (mats {n0-7/k0-7, n0-7/k8-15, n8-15/k0-7, n8-15/k8-15})
    const int n_local = (lane >> 4) * 8 + (lane & 7);
    const uint32_t b_addr =
        sb + (uint32_t)(n_local * ROWB + ((lane >> 3) & 1) * 16);
    // A fragment source coordinates in XF (canonical m16n8k16 A map)
    const int ar = wrow + (lane >> 2);              // rows ar, ar+8
    const int ac = (lane & 3) * 2;                  // k cols ac, ac+1 (+8)
    // C store coordinates (canonical C map)
    const int cr = wrow + (lane >> 2);
    const int cc = (lane & 3) * 2;

    uint32_t xf_cur  = sb + SM_XF0;
    uint32_t xf_next = sb + SM_XF1;

    // ---- Persistent tile loop ----
    for (int t = bx; t < NTILES; t += GRID_X) {
        const int tok0 = t * BLK_TOK;

        cp_wait_all();          // tile t in xf_cur (in flight a full iter)
        __syncthreads();        // the ONLY per-tile barrier: makes XF visible
                                // to all warps, and orders prior-iter work
                                // before xf_next is overwritten below.

        // Kick next prefetch immediately: full-iteration-deep pipeline.
        if (t + GRID_X < NTILES)
            prefetch_tile(xf_next, x, g, (t + GRID_X) * BLK_TOK, tid);

        // ---- Build A fragments in registers (trunc split) ----
        uint4 AH[4], AL[4];
        {
            const float* xf = reinterpret_cast<const float*>(
                smem + (xf_cur - sb));
            #pragma unroll
            for (int kk = 0; kk < 4; kk++) {
                const float* p0 = xf + ar * XF_STRIDE + kk * 16 + ac;
                const float* p1 = xf + (ar + 8) * XF_STRIDE + kk * 16 + ac;
                float2 f0 = *reinterpret_cast<const float2*>(p0);
                float2 f1 = *reinterpret_cast<const float2*>(p1);
                float2 f2 = *reinterpret_cast<const float2*>(p0 + 8);
                float2 f3 = *reinterpret_cast<const float2*>(p1 + 8);
                split2t(f0, AH[kk].x, AL[kk].x);    // rows ar,   k low
                split2t(f1, AH[kk].y, AL[kk].y);    // rows ar+8, k low
                split2t(f2, AH[kk].z, AL[kk].z);    // rows ar,   k high
                split2t(f3, AH[kk].w, AL[kk].w);    // rows ar+8, k high
            }
        }

        // ---- Mainloop: 4 independent acc chains per np-pair ----
        float acc[8][4];
        #pragma unroll
        for (int nt = 0; nt < 8; nt++)
            #pragma unroll
            for (int i = 0; i < 4; i++)
                acc[nt][i] = 0.0f;

        #pragma unroll
        for (int kk = 0; kk < 4; kk++) {
            const uint32_t kb = kk * 32;            // 16 bf16 = 32 B
            const uint4 ah = AH[kk];
            const uint4 al = AL[kk];
            #pragma unroll
            for (int npp = 0; npp < 2; npp++) {
                const uint32_t o0 = (npp * 2) * 16 * ROWB + kb;
                const uint32_t o1 = (npp * 2 + 1) * 16 * ROWB + kb;
                uint4 bh0 = ldm_x4(b_addr + SM_WH + o0);
                uint4 bh1 = ldm_x4(b_addr + SM_WH + o1);
                uint4 bl0 = ldm_x4(b_addr + SM_WL + o0);
                uint4 bl1 = ldm_x4(b_addr + SM_WL + o1);
                float* c0 = acc[npp * 4 + 0];
                float* c1 = acc[npp * 4 + 1];
                float* c2 = acc[npp * 4 + 2];
                float* c3 = acc[npp * 4 + 3];
                mma_bf16(c0, ah, bh0.x, bh0.y);     // hi*hi
                mma_bf16(c1, ah, bh0.z, bh0.w);
                mma_bf16(c2, ah, bh1.x, bh1.y);
                mma_bf16(c3, ah, bh1.z, bh1.w);
                mma_bf16(c0, ah, bl0.x, bl0.y);     // hi*lo
                mma_bf16(c1, ah, bl0.z, bl0.w);
                mma_bf16(c2, ah, bl1.x, bl1.y);
                mma_bf16(c3, ah, bl1.z, bl1.w);
                mma_bf16(c0, al, bh0.x, bh0.y);     // lo*hi
                mma_bf16(c1, al, bh0.z, bh0.w);
                mma_bf16(c2, al, bh1.x, bh1.y);
                mma_bf16(c3, al, bh1.z, bh1.w);
            }
        }

        // ---- Epilogue: direct register -> global stores ----
        // Chain cix covers N-cols n0 = (cix/4)*32 + (cix%4)*8; regs {0,1} are
        // row cr, regs {2,3} row cr+8. Per warp instruction: 8 rows x 32B
        // fully-used sectors -> sector-perfect without staging.
        {
            float* yrow0 = y + (size_t)(tok0 + cr) * IN_CH + g * GS + cc;
            float* yrow1 = yrow0 + (size_t)8 * IN_CH;
            #pragma unroll
            for (int cix = 0; cix < 8; cix++) {
                int n0 = (cix >> 2) * 32 + (cix & 3) * 8;
                *reinterpret_cast<float2*>(yrow0 + n0) =
                    make_float2(acc[cix][0], acc[cix][1]);
                *reinterpret_cast<float2*>(yrow1 + n0) =
                    make_float2(acc[cix][2], acc[cix][3]);
            }
        }

        // swap buffers; next iter's top sync orders everything.
        uint32_t tmp = xf_cur; xf_cur = xf_next; xf_next = tmp;
    }
}

extern "C" void kernel_launch(void* const* d_in, const int* in_sizes, int n_in,
                              void* d_out, int out_size) {
    const float* x = (const float*)d_in[0];   // [8192, 4096] fp32
    const float* w = (const float*)d_in[1];   // [4096, 4096] fp32
    float* y = (float*)d_out;                 // [8192, 4096] fp32

    cudaFuncSetAttribute(group_linear_mma,
                         cudaFuncAttributeMaxDynamicSharedMemorySize, SM_TOTAL);
    dim3 grid(GRID_X, GROUPS);                // (9, 64) persistent CTAs
    group_linear_mma<<<grid, THREADS, SM_TOTAL>>>(x, w, y);
}